// round 17
// baseline (speedup 1.0000x reference)
#include <cuda_runtime.h>
#include <cstdint>

#define Bb    8
#define Hh    512
#define Ll    8192
#define NFFT  16384
#define HALF  8192
#define QTOP  4096
#define NPAIR 256
#define TFFT  512    /* kf kernel threads */
#define TC    256    /* conv kernel threads */
#define NTW   5461

// ---------------- scratch (device globals; no allocation allowed) ----------------
__device__ float2 g_Kf[(size_t)Hh * (HALF + 1)];        // raw rfft of K per channel (k=0..8192)
__device__ float4 g_GDa[(size_t)Hh * 4097];             // gamma/delta for slot1's k, iteration order
__device__ float4 g_GDb[(size_t)Hh * 4097];             // gamma/delta for partner's k
__device__ float  g_ymid[(size_t)Bb * Hh * Ll];         // conv+skip result, tf32-rounded
__device__ float  g_Wr[(size_t)Hh * Hh];                // W pre-rounded to tf32 (rna)
__device__ float2 g_tw1[NTW];
__device__ float2 g_tw2[NTW];
__device__ float2 g_tw3[NTW];

// ---------------- helpers ----------------
__device__ __forceinline__ float2 cmulf(float2 a, float2 b) {
    return make_float2(a.x * b.x - a.y * b.y, a.x * b.y + a.y * b.x);
}
__device__ __forceinline__ int rev4_14(int k) {
    unsigned r = __brev((unsigned)k) >> 18;
    return (int)(((r & 0x2AAAu) >> 1) | ((r & 0x1555u) << 1));
}
__device__ __forceinline__ int rev4_12(int k) {
    unsigned r = __brev((unsigned)k) >> 20;
    return (int)(((r & 0xAAAu) >> 1) | ((r & 0x555u) << 1));
}
__device__ __forceinline__ float tf32r(float v) {
    uint32_t r;
    asm("cvt.rna.tf32.f32 %0, %1;" : "=r"(r) : "f"(v));
    return __uint_as_float(r);
}
// full-nibble bank swizzle (involution)
__device__ __forceinline__ int sw(int n) {
    return n ^ ((n >> 4) & 15);
}
__device__ __forceinline__ void bf4(float2& a0, float2& a1, float2& a2, float2& a3) {
    float t0x = a0.x + a2.x, t0y = a0.y + a2.y;
    float t1x = a0.x - a2.x, t1y = a0.y - a2.y;
    float t2x = a1.x + a3.x, t2y = a1.y + a3.y;
    float t3x = a1.x - a3.x, t3y = a1.y - a3.y;
    a0 = make_float2(t0x + t2x, t0y + t2y);
    a1 = make_float2(t1x + t3y, t1y - t3x);
    a2 = make_float2(t0x - t2x, t0y - t2y);
    a3 = make_float2(t1x - t3y, t1y + t3x);
}

// ---------------- twiddle LUT init ----------------
__global__ void tw_init() {
    int idx = blockIdx.x * 256 + threadIdx.x;
    if (idx >= NTW) return;
    int q = 1, off = 0;
    while (idx >= off + q) { off += q; q <<= 2; }
    int j = idx - off;
    int m = q << 2;
    float ang = -6.283185307179586f * ((float)j / (float)m);
    float s1, c1, s2, c2, s3, c3;
    sincosf(ang, &s1, &c1);
    sincosf(2.0f * ang, &s2, &c2);
    sincosf(3.0f * ang, &s3, &c3);
    g_tw1[idx] = make_float2(c1, s1);
    g_tw2[idx] = make_float2(c2, s2);
    g_tw3[idx] = make_float2(c3, s3);
}

// ================= kf: 16384-point FFT of packed channel pair -> raw Kf spectra =================
__device__ void kf_dif_first(float2* s, const float* __restrict__ f1,
                             const float* __restrict__ f2, int tid) {
#pragma unroll 4
    for (int i = tid; i < QTOP; i += TFFT) {
        float2 a0 = make_float2(f1[i], f2[i]);
        float2 a1 = make_float2(f1[i + QTOP], f2[i + QTOP]);
        float2 b0 = make_float2(a0.x + a1.x, a0.y + a1.y);
        float2 b1 = make_float2(a0.x + a1.y, a0.y - a1.x);
        float2 b2 = make_float2(a0.x - a1.x, a0.y - a1.y);
        float2 b3 = make_float2(a0.x - a1.y, a0.y + a1.x);
        float2 w1 = __ldg(&g_tw1[1365 + i]);
        float2 w2 = __ldg(&g_tw2[1365 + i]);
        float2 w3 = __ldg(&g_tw3[1365 + i]);
        int ib = i ^ ((i >> 4) & 15);
        s[ib]            = b0;
        s[ib + QTOP]     = cmulf(b1, w1);
        s[ib + 2 * QTOP] = cmulf(b2, w2);
        s[ib + 3 * QTOP] = cmulf(b3, w3);
    }
    __syncthreads();
}

template<int Q>
__device__ __forceinline__ void kf_dif_merged(float2* s, int tid) {
    constexpr int Q4   = Q / 4;
    constexpr int offA = (Q - 1) / 3;
    constexpr int offB = (Q4 - 1) / 3;
#pragma unroll 1
    for (int i = tid; i < NFFT / 16; i += TFFT) {
        int j  = i & (Q4 - 1);
        int g0 = (i / Q4) * (16 * Q4) + j;
        float2 x[16];
#pragma unroll
        for (int b = 0; b < 4; ++b) {
            float2 a0 = s[sw(g0 + b * Q4)];
            float2 a1 = s[sw(g0 + b * Q4 + Q)];
            float2 a2 = s[sw(g0 + b * Q4 + 2 * Q)];
            float2 a3 = s[sw(g0 + b * Q4 + 3 * Q)];
            bf4(a0, a1, a2, a3);
            int jA = j + b * Q4;
            float2 w1 = __ldg(&g_tw1[offA + jA]);
            float2 w2 = __ldg(&g_tw2[offA + jA]);
            float2 w3 = __ldg(&g_tw3[offA + jA]);
            x[b]      = a0;
            x[4 + b]  = cmulf(a1, w1);
            x[8 + b]  = cmulf(a2, w2);
            x[12 + b] = cmulf(a3, w3);
        }
        float2 v1 = __ldg(&g_tw1[offB + j]);
        float2 v2 = __ldg(&g_tw2[offB + j]);
        float2 v3 = __ldg(&g_tw3[offB + j]);
#pragma unroll
        for (int a = 0; a < 4; ++a) {
            bf4(x[4 * a], x[4 * a + 1], x[4 * a + 2], x[4 * a + 3]);
            int n0 = g0 + a * Q;
            s[sw(n0)]           = x[4 * a];
            s[sw(n0 + Q4)]      = cmulf(x[4 * a + 1], v1);
            s[sw(n0 + 2 * Q4)]  = cmulf(x[4 * a + 2], v2);
            s[sw(n0 + 3 * Q4)]  = cmulf(x[4 * a + 3], v3);
        }
    }
    __syncthreads();
}

// kf_kernel: raw Kf1,Kf2 (k=0..8192) for channels 2p, 2p+1
__global__ void __launch_bounds__(TFFT, 1) kf_kernel(const float* __restrict__ K) {
    extern __shared__ float2 s[];
    int tid  = threadIdx.x;
    int pair = blockIdx.x;
    const float* k1 = K + (size_t)(2 * pair) * Ll;
    const float* k2 = K + (size_t)(2 * pair + 1) * Ll;
    kf_dif_first(s, k1, k2, tid);
    kf_dif_merged<1024>(s, tid);
    kf_dif_merged<64>(s, tid);
    kf_dif_merged<4>(s, tid);

    float2* Kf1 = g_Kf + (size_t)(2 * pair) * (HALF + 1);
    float2* Kf2 = g_Kf + (size_t)(2 * pair + 1) * (HALF + 1);
#pragma unroll 2
    for (int k = tid; k <= HALF; k += TFFT) {
        int pk  = rev4_14(k);
        int kn  = (NFFT - k) & (NFFT - 1);
        int pk2 = rev4_14(kn);
        float2 Zk = s[sw(pk)];
        float2 Zp = s[sw(pk2)];
        Kf1[k] = make_float2(0.5f * (Zk.x + Zp.x), 0.5f * (Zk.y - Zp.y));
        Kf2[k] = make_float2(0.5f * (Zk.y + Zp.y), 0.5f * (Zp.x - Zk.x));
    }
}

// ================= gd: per-channel combined pointwise coefficients =================
// Zv[k] = gamma_k Z[k] + delta_k conj(Z[8192-k]) for the 8192-point packed conv chain.
__device__ __forceinline__ float4 gd_coef(const float2* __restrict__ Kf, int k) {
    float2 F1 = Kf[k];
    float2 F2c = Kf[HALF - k];
    float2 F2 = make_float2(F2c.x, -F2c.y);          // conj(Kf[8192-k])
    float ang = 6.283185307179586f * ((float)k / (float)NFFT);
    float s_, c_;
    sincosf(ang, &s_, &c_);                          // w = e^{+2pi i k/16384}
    float2 A1 = make_float2(1.f - s_,  c_);          // 1 + i w
    float2 A2 = make_float2(1.f + s_, -c_);          // 1 - i w
    float2 p  = make_float2(0.5f * (1.f - s_), -0.5f * c_);   // (1 - i conj(w))/2
    float2 q  = make_float2(0.5f * (1.f + s_),  0.5f * c_);   // (1 + i conj(w))/2
    float2 t1 = cmulf(F1, A1);
    float2 t2 = cmulf(F2, A2);
    const float inv = 1.0f / (float)NFFT;
    float2 ga = make_float2((t1.x * p.x - t1.y * p.y + t2.x * q.x - t2.y * q.y) * inv,
                            (t1.x * p.y + t1.y * p.x + t2.x * q.y + t2.y * q.x) * inv);
    float2 de = make_float2((t1.x * q.x - t1.y * q.y + t2.x * p.x - t2.y * p.y) * inv,
                            (t1.x * q.y + t1.y * q.x + t2.x * p.y + t2.y * p.x) * inv);
    return make_float4(ga.x, ga.y, de.x, de.y);
}

__global__ void gd_kernel() {
    int h = blockIdx.x;
    const float2* Kf = g_Kf + (size_t)h * (HALF + 1);
    float4* GA = g_GDa + (size_t)h * 4097;
    float4* GB = g_GDb + (size_t)h * 4097;
    for (int i = threadIdx.x; i < 4097; i += 256) {
        int k, kp;
        if (i < 2048) {
            int pe = ((i >> 1) << 2) | (i & 1);
            int kk = rev4_12(pe);
            k  = 2 * kk;
            kp = (HALF - k) & (HALF - 1);
        } else if (i < 4096) {
            int ii = i - 2048;
            int sg = ((ii >> 1) << 2) | (ii & 1);
            k  = 2 * rev4_12(sg) + 1;
            kp = HALF - k;
        } else {
            k = 4096; kp = 4096;
        }
        GA[i] = gd_coef(Kf, k);
        GB[i] = gd_coef(Kf, kp);
    }
}

// ================= conv: one channel per CTA, 8192-point packed FFT, 64 KB smem =================
// merged radix-16 passes over the two independent 4096 blocks (radix-2 stage fused at ends).
template<int Q>
__device__ __forceinline__ void c_dif_merged(float2* s, int tid) {
    constexpr int Q4   = Q / 4;
    constexpr int offA = (Q - 1) / 3;
    constexpr int offB = (Q4 - 1) / 3;
#pragma unroll 1
    for (int i = tid; i < 512; i += TC) {
        int blk = i >> 8, ii = i & 255;
        int j  = ii & (Q4 - 1);
        int g0 = blk * 4096 + (ii / Q4) * (16 * Q4) + j;
        float2 x[16];
#pragma unroll
        for (int b = 0; b < 4; ++b) {
            float2 a0 = s[sw(g0 + b * Q4)];
            float2 a1 = s[sw(g0 + b * Q4 + Q)];
            float2 a2 = s[sw(g0 + b * Q4 + 2 * Q)];
            float2 a3 = s[sw(g0 + b * Q4 + 3 * Q)];
            bf4(a0, a1, a2, a3);
            int jA = j + b * Q4;
            float2 w1 = __ldg(&g_tw1[offA + jA]);
            float2 w2 = __ldg(&g_tw2[offA + jA]);
            float2 w3 = __ldg(&g_tw3[offA + jA]);
            x[b]      = a0;
            x[4 + b]  = cmulf(a1, w1);
            x[8 + b]  = cmulf(a2, w2);
            x[12 + b] = cmulf(a3, w3);
        }
        float2 v1 = __ldg(&g_tw1[offB + j]);
        float2 v2 = __ldg(&g_tw2[offB + j]);
        float2 v3 = __ldg(&g_tw3[offB + j]);
#pragma unroll
        for (int a = 0; a < 4; ++a) {
            bf4(x[4 * a], x[4 * a + 1], x[4 * a + 2], x[4 * a + 3]);
            int n0 = g0 + a * Q;
            s[sw(n0)]           = x[4 * a];
            s[sw(n0 + Q4)]      = cmulf(x[4 * a + 1], v1);
            s[sw(n0 + 2 * Q4)]  = cmulf(x[4 * a + 2], v2);
            s[sw(n0 + 3 * Q4)]  = cmulf(x[4 * a + 3], v3);
        }
    }
    __syncthreads();
}

template<int Q>
__device__ __forceinline__ void c_dit_merged(float2* s, int tid) {
    constexpr int Q4   = Q / 4;
    constexpr int offA = (Q - 1) / 3;
    constexpr int offB = (Q4 - 1) / 3;
#pragma unroll 1
    for (int i = tid; i < 512; i += TC) {
        int blk = i >> 8, ii = i & 255;
        int j  = ii & (Q4 - 1);
        int g0 = blk * 4096 + (ii / Q4) * (16 * Q4) + j;
        float2 x[16];
        float2 v1 = __ldg(&g_tw1[offB + j]);
        float2 v2 = __ldg(&g_tw2[offB + j]);
        float2 v3 = __ldg(&g_tw3[offB + j]);
#pragma unroll
        for (int a = 0; a < 4; ++a) {
            int n0 = g0 + a * Q;
            float2 c0 = s[sw(n0)];
            float2 c1 = s[sw(n0 + Q4)];
            float2 c2 = s[sw(n0 + 2 * Q4)];
            float2 c3 = s[sw(n0 + 3 * Q4)];
            c1 = cmulf(c1, v1);
            c2 = cmulf(c2, v2);
            c3 = cmulf(c3, v3);
            bf4(c0, c1, c2, c3);
            x[4 * a]     = c0;
            x[4 * a + 1] = c1;
            x[4 * a + 2] = c2;
            x[4 * a + 3] = c3;
        }
#pragma unroll
        for (int b = 0; b < 4; ++b) {
            int jA = j + b * Q4;
            float2 w1 = __ldg(&g_tw1[offA + jA]);
            float2 w2 = __ldg(&g_tw2[offA + jA]);
            float2 w3 = __ldg(&g_tw3[offA + jA]);
            float2 c0 = x[b];
            float2 c1 = cmulf(x[4 + b],  w1);
            float2 c2 = cmulf(x[8 + b],  w2);
            float2 c3 = cmulf(x[12 + b], w3);
            bf4(c0, c1, c2, c3);
            int n0 = g0 + b * Q4;
            s[sw(n0)]         = c0;
            s[sw(n0 + Q)]     = c1;
            s[sw(n0 + 2 * Q)] = c2;
            s[sw(n0 + 3 * Q)] = c3;
        }
    }
    __syncthreads();
}

#define CONV_SMEM (8192 * 8)

__global__ void __launch_bounds__(TC, 3) conv_kernel(const float* __restrict__ u,
                                                     const float* __restrict__ D) {
    extern __shared__ float2 s[];
    int tid = threadIdx.x;
    int h = blockIdx.x & (Hh - 1);
    int b = blockIdx.x >> 9;
    const float2* uz = (const float2*)(u + ((size_t)b * Hh + h) * Ll);  // 4096 float2

    // load + unpack + radix-2 DIF stage (m=8192, top half zero): w2_n = e^{-2pi i n/8192} = g_tw2 row
#pragma unroll 2
    for (int n = tid; n < 4096; n += TC) {
        float2 z  = uz[n];
        float2 w2 = __ldg(&g_tw2[1365 + n]);
        s[sw(n)]        = z;
        s[sw(n + 4096)] = cmulf(z, w2);
    }
    __syncthreads();

    c_dif_merged<1024>(s, tid);
    c_dif_merged<64>(s, tid);
    c_dif_merged<4>(s, tid);

    // pointwise: Zv[k] = gamma Z[k] + delta conj(Z[8192-k]); store conj(Zv)
    const float4* GA = g_GDa + (size_t)h * 4097;
    const float4* GB = g_GDb + (size_t)h * 4097;
#pragma unroll 2
    for (int i = tid; i < 4096; i += TC) {
        int s1, s2;
        if (i < 2048) {
            int pe = ((i >> 1) << 2) | (i & 1);
            int kk = rev4_12(pe);
            s1 = pe;
            s2 = rev4_12((4096 - kk) & 4095);
        } else {
            int ii = i - 2048;
            int sg = ((ii >> 1) << 2) | (ii & 1);
            s1 = 4096 + sg;
            s2 = 4096 + (4095 - sg);
        }
        float4 ga = GA[i];
        float4 gb = GB[i];
        int a1 = sw(s1), a2 = sw(s2);
        float2 Z1 = s[a1];
        float2 Z2 = s[a2];
        float v1x = ga.x * Z1.x - ga.y * Z1.y + ga.z * Z2.x + ga.w * Z2.y;
        float v1y = ga.x * Z1.y + ga.y * Z1.x - ga.z * Z2.y + ga.w * Z2.x;
        s[a1] = make_float2(v1x, -v1y);
        if (s1 != s2) {
            float v2x = gb.x * Z2.x - gb.y * Z2.y + gb.z * Z1.x + gb.w * Z1.y;
            float v2y = gb.x * Z2.y + gb.y * Z2.x - gb.z * Z1.y + gb.w * Z1.x;
            s[a2] = make_float2(v2x, -v2y);
        }
    }
    if (tid == 0) {  // k = 4096 (slot 2), self-paired
        float4 ga = GA[4096];
        int a = sw(2);
        float2 Z = s[a];
        float vx = ga.x * Z.x - ga.y * Z.y + ga.z * Z.x + ga.w * Z.y;
        float vy = ga.x * Z.y + ga.y * Z.x - ga.z * Z.y + ga.w * Z.x;
        s[a] = make_float2(vx, -vy);
    }
    __syncthreads();

    c_dit_merged<4>(s, tid);
    c_dit_merged<64>(s, tid);
    c_dit_merged<1024>(s, tid);

    // fused last radix-2 DIT stage + real unpack + skip; outputs n<4096 only (rest = circular garbage)
    float d = D[h];
    float2* yz = (float2*)(g_ymid + ((size_t)b * Hh + h) * Ll);
#pragma unroll 2
    for (int n = tid; n < 4096; n += TC) {
        float2 c0 = s[sw(n)];
        float2 c1 = s[sw(n + 4096)];
        float2 w2 = __ldg(&g_tw2[1365 + n]);
        float2 t  = cmulf(c1, w2);
        float rx = c0.x + t.x;          // res = conj(y[2n] + i y[2n+1])
        float ry = c0.y + t.y;
        float2 z = uz[n];
        yz[n] = make_float2(tf32r(rx + d * z.x), tf32r(-ry + d * z.y));
    }
}

// ---------------- pre-round W to tf32 ----------------
__global__ void wround_kernel(const float* __restrict__ W) {
    int i = blockIdx.x * 256 + threadIdx.x;
    g_Wr[i] = tf32r(W[i]);
}

// ================= mix: tf32 mma.sync GEMM + tanh (unchanged from R16) =================
#define MIXT 128
#define NCHK (Hh / 32)
#define AS_STR 36
#define BS_STR 136
#define A_BYTES (128 * AS_STR * 4)
#define B_BYTES (32 * BS_STR * 4)
#define STAGE_BYTES (A_BYTES + B_BYTES)
#define MIX_SMEM (3 * STAGE_BYTES)

__device__ __forceinline__ void mma_tf32(float* c, const uint32_t* a, const uint32_t* b) {
    asm volatile(
        "mma.sync.aligned.m16n8k8.row.col.f32.tf32.tf32.f32 "
        "{%0,%1,%2,%3}, {%4,%5,%6,%7}, {%8,%9}, {%0,%1,%2,%3};"
        : "+f"(c[0]), "+f"(c[1]), "+f"(c[2]), "+f"(c[3])
        : "r"(a[0]), "r"(a[1]), "r"(a[2]), "r"(a[3]), "r"(b[0]), "r"(b[1]));
}
__device__ __forceinline__ void load_stage(const float* __restrict__ Wp,
                                           const float* __restrict__ Yp,
                                           uint32_t smem_stage, int c, int tid) {
    int k0 = c * 32;
#pragma unroll
    for (int i = 0; i < 8; ++i) {
        int idx = tid + i * MIXT;
        int row = idx >> 3, seg = idx & 7;
        const float* src = Wp + (size_t)row * Hh + k0 + seg * 4;
        uint32_t dst = smem_stage + (uint32_t)(row * AS_STR + seg * 4) * 4;
        asm volatile("cp.async.cg.shared.global [%0], [%1], 16;" :: "r"(dst), "l"(src));
    }
#pragma unroll
    for (int i = 0; i < 8; ++i) {
        int idx = tid + i * MIXT;
        int row = idx >> 5, seg = idx & 31;
        const float* src = Yp + (size_t)(k0 + row) * Ll + seg * 4;
        uint32_t dst = smem_stage + A_BYTES + (uint32_t)(row * BS_STR + seg * 4) * 4;
        asm volatile("cp.async.cg.shared.global [%0], [%1], 16;" :: "r"(dst), "l"(src));
    }
    asm volatile("cp.async.commit_group;" ::: "memory");
}

__global__ void __launch_bounds__(MIXT, 2) mix_tc_kernel(float* __restrict__ out) {
    extern __shared__ char smx[];
    uint32_t sb;
    asm("{ .reg .u64 t; cvta.to.shared.u64 t, %1; cvt.u32.u64 %0, t; }" : "=r"(sb) : "l"(smx));
    int tid  = threadIdx.x;
    int lane = tid & 31, wid = tid >> 5;
    int warpM = wid >> 1, warpN = wid & 1;
    int g = lane >> 2, tg = lane & 3;

    int b     = blockIdx.z;
    int pTile = blockIdx.y * 128;
    int lTile = blockIdx.x * 128;
    const float* Wp = g_Wr + (size_t)pTile * Hh;
    const float* Yp = g_ymid + (size_t)b * Hh * Ll + lTile;
    float* Ob = out + (size_t)b * Hh * Ll;

    float acc[4][8][4];
#pragma unroll
    for (int mt = 0; mt < 4; ++mt)
#pragma unroll
        for (int nt = 0; nt < 8; ++nt)
#pragma unroll
            for (int r = 0; r < 4; ++r) acc[mt][nt][r] = 0.f;

    load_stage(Wp, Yp, sb, 0, tid);
    load_stage(Wp, Yp, sb + STAGE_BYTES, 1, tid);

#pragma unroll 1
    for (int c = 0; c < NCHK; ++c) {
        if (c < NCHK - 2) {
            asm volatile("cp.async.wait_group 1;" ::: "memory");
        } else {
            asm volatile("cp.async.wait_group 0;" ::: "memory");
        }
        __syncthreads();
        if (c + 2 < NCHK)
            load_stage(Wp, Yp, sb + (uint32_t)((c + 2) % 3) * STAGE_BYTES, c + 2, tid);

        const float* As = (const float*)(smx + (c % 3) * STAGE_BYTES);
        const float* Bs = (const float*)(smx + (c % 3) * STAGE_BYTES + A_BYTES);
#pragma unroll
        for (int ks = 0; ks < 4; ++ks) {
            uint32_t af[4][4], bf[8][2];
            int kc = ks * 8 + tg;
#pragma unroll
            for (int mt = 0; mt < 4; ++mt) {
                int r0 = warpM * 64 + mt * 16 + g;
                af[mt][0] = __float_as_uint(As[r0 * AS_STR + kc]);
                af[mt][1] = __float_as_uint(As[(r0 + 8) * AS_STR + kc]);
                af[mt][2] = __float_as_uint(As[r0 * AS_STR + kc + 4]);
                af[mt][3] = __float_as_uint(As[(r0 + 8) * AS_STR + kc + 4]);
            }
#pragma unroll
            for (int nt = 0; nt < 8; ++nt) {
                int l = warpN * 64 + nt * 8 + g;
                bf[nt][0] = __float_as_uint(Bs[kc * BS_STR + l]);
                bf[nt][1] = __float_as_uint(Bs[(kc + 4) * BS_STR + l]);
            }
#pragma unroll
            for (int mt = 0; mt < 4; ++mt)
#pragma unroll
                for (int nt = 0; nt < 8; ++nt)
                    mma_tf32(acc[mt][nt], af[mt], bf[nt]);
        }
    }

#pragma unroll
    for (int mt = 0; mt < 4; ++mt) {
        int p0 = pTile + warpM * 64 + mt * 16 + g;
#pragma unroll
        for (int nt = 0; nt < 8; ++nt) {
            int l = lTile + warpN * 64 + nt * 8 + 2 * tg;
            float2 v0 = make_float2(tanhf(acc[mt][nt][0]), tanhf(acc[mt][nt][1]));
            float2 v1 = make_float2(tanhf(acc[mt][nt][2]), tanhf(acc[mt][nt][3]));
            *(float2*)(Ob + (size_t)p0 * Ll + l)       = v0;
            *(float2*)(Ob + (size_t)(p0 + 8) * Ll + l) = v1;
        }
    }
}

// ---------------- launch ----------------
extern "C" void kernel_launch(void* const* d_in, const int* in_sizes, int n_in,
                              void* d_out, int out_size) {
    const float* u = (const float*)d_in[0];
    const float* K = (const float*)d_in[1];
    const float* D = (const float*)d_in[2];
    const float* W = (const float*)d_in[3];
    float* out = (float*)d_out;

    const int kf_smem = NFFT * (int)sizeof(float2);   // 128 KB (kf only)
    cudaFuncSetAttribute(kf_kernel,   cudaFuncAttributeMaxDynamicSharedMemorySize, kf_smem);
    cudaFuncSetAttribute(conv_kernel, cudaFuncAttributeMaxDynamicSharedMemorySize, CONV_SMEM);
    cudaFuncSetAttribute(mix_tc_kernel, cudaFuncAttributeMaxDynamicSharedMemorySize, MIX_SMEM);

    tw_init<<<(NTW + 255) / 256, 256>>>();
    wround_kernel<<<(Hh * Hh) / 256, 256>>>(W);
    kf_kernel<<<NPAIR, TFFT, kf_smem>>>(K);
    gd_kernel<<<Hh, 256>>>();
    conv_kernel<<<Bb * Hh, TC, CONV_SMEM>>>(u, D);
    dim3 g(Ll / 128, Hh / 128, Bb);
    mix_tc_kernel<<<g, MIXT, MIX_SMEM>>>(out);
}